// round 16
// baseline (speedup 1.0000x reference)
#include <cuda_runtime.h>
#include <cuda_bf16.h>
#include <cstdint>

#define NROWS   32768
#define KCODES  8192
#define DIM     256
#define NTILES  64             // KCODES / 128
#define MARGIN  1.0f
#define DECAY_F 0.99f
#define OMD_F   0.01f
#define EPSV    1e-5f
#define CCOST   0.25f

// output layout (flattened, reference return order, all f32)
#define ZQ_OFF    0
#define LOSS_OFF  8388608
#define IDX_OFF   8388609
#define NEMB_OFF  8421377
#define NCS_OFF   10518529
#define NEMAW_OFF 10526721

// ---------------- scratch (static device globals; no allocs) ----------------
__device__ unsigned long long g_keys[NROWS];
__device__ unsigned long long g_part[NROWS * NTILES];   // per (row, tile) approx min-key
__device__ int g_tcnt[NTILES];
__device__ int g_tlist[NTILES * NROWS];
__device__ float g_h[KCODES];
__device__ float g_counts[KCODES];
__device__ float g_dw[KCODES * DIM];
__device__ float g_loss_sum;
__device__ float g_n_tot;
__device__ __nv_bfloat16 g_Ah[NROWS * DIM];    // z_hi (bf16), 512B rows
__device__ __nv_bfloat16 g_Bh[KCODES * DIM];   // e_hi (bf16), 512B rows

// ---------------- helpers ----------------
__device__ __forceinline__ unsigned int fkey(float f) {
    unsigned int u = __float_as_uint(f);
    return (u & 0x80000000u) ? ~u : (u | 0x80000000u);
}
__device__ __forceinline__ float inv_fkey(unsigned int k) {
    unsigned int u = (k & 0x80000000u) ? (k & 0x7FFFFFFFu) : ~k;
    return __uint_as_float(u);
}
__device__ __forceinline__ unsigned long long ullmin2(unsigned long long a,
                                                      unsigned long long b) {
    return a < b ? a : b;
}
__device__ __forceinline__ uint32_t smem_u32(const void* p) {
    uint32_t a;
    asm("{ .reg .u64 t; cvta.to.shared.u64 t, %1; cvt.u32.u64 %0, t; }"
        : "=r"(a) : "l"(p));
    return a;
}
__device__ __forceinline__ void cp_async16(uint32_t smem, const void* g) {
    asm volatile("cp.async.cg.shared.global [%0], [%1], 16;"
                 :: "r"(smem), "l"(g));
}
__device__ __forceinline__ void cp_commit() {
    asm volatile("cp.async.commit_group;");
}
__device__ __forceinline__ void cp_wait1() {
    asm volatile("cp.async.wait_group 1;");
}
__device__ __forceinline__ void cp_wait0() {
    asm volatile("cp.async.wait_group 0;");
}
__device__ __forceinline__ void ldsm4(uint32_t& r0, uint32_t& r1, uint32_t& r2,
                                      uint32_t& r3, uint32_t addr) {
    asm volatile("ldmatrix.sync.aligned.m8n8.x4.shared.b16 {%0,%1,%2,%3}, [%4];"
                 : "=r"(r0), "=r"(r1), "=r"(r2), "=r"(r3) : "r"(addr));
}
__device__ __forceinline__ void mma16816(float& c0, float& c1, float& c2, float& c3,
                                         uint32_t a0, uint32_t a1, uint32_t a2,
                                         uint32_t a3, uint32_t b0, uint32_t b1) {
    asm volatile(
        "mma.sync.aligned.m16n8k16.row.col.f32.bf16.bf16.f32 "
        "{%0,%1,%2,%3}, {%4,%5,%6,%7}, {%8,%9}, {%0,%1,%2,%3};"
        : "+f"(c0), "+f"(c1), "+f"(c2), "+f"(c3)
        : "r"(a0), "r"(a1), "r"(a2), "r"(a3), "r"(b0), "r"(b1));
}

// ---------------- K0: zero scratch ----------------
__global__ void init_kernel() {
    int i = blockIdx.x * blockDim.x + threadIdx.x;
    if (i < KCODES * DIM) g_dw[i] = 0.0f;
    if (i < NROWS * NTILES) g_part[i] = 0xFFFFFFFFFFFFFFFFull;
    if (i < NROWS) g_keys[i] = 0xFFFFFFFFFFFFFFFFull;
    if (i < KCODES) g_counts[i] = 0.0f;
    if (i < NTILES) g_tcnt[i] = 0;
    if (i == 0) g_loss_sum = 0.0f;
}

// ---------------- K0b: bf16 hi pack ----------------
__global__ void pack_z_kernel(const float* __restrict__ z) {
    int i = blockIdx.x * blockDim.x + threadIdx.x;
    if (i >= NROWS * DIM / 4) return;
    float4 v = reinterpret_cast<const float4*>(z)[i];
    __nv_bfloat162 h0 = __float22bfloat162_rn(make_float2(v.x, v.y));
    __nv_bfloat162 h1 = __float22bfloat162_rn(make_float2(v.z, v.w));
    __nv_bfloat162* d = reinterpret_cast<__nv_bfloat162*>(&g_Ah[i * 4]);
    d[0] = h0; d[1] = h1;
}
__global__ void pack_e_kernel(const float* __restrict__ e) {
    int i = blockIdx.x * blockDim.x + threadIdx.x;
    if (i >= KCODES * DIM / 4) return;
    float4 v = reinterpret_cast<const float4*>(e)[i];
    __nv_bfloat162 h0 = __float22bfloat162_rn(make_float2(v.x, v.y));
    __nv_bfloat162 h1 = __float22bfloat162_rn(make_float2(v.z, v.w));
    __nv_bfloat162* d = reinterpret_cast<__nv_bfloat162*>(&g_Bh[i * 4]);
    d[0] = h0; d[1] = h1;
}

// ---------------- K1: h[k] = 0.5*|e_k|^2 (exact fp32) ----------------
__global__ void h_kernel(const float* __restrict__ emb) {
    int lane = threadIdx.x & 31;
    int n = blockIdx.x * 8 + (threadIdx.x >> 5);
    float s = 0.0f;
#pragma unroll
    for (int j = 0; j < 8; j++) {
        float v = emb[n * DIM + lane + j * 32];
        s += v * v;
    }
#pragma unroll
    for (int off = 16; off; off >>= 1) s += __shfl_down_sync(0xFFFFFFFFu, s, off);
    if (lane == 0) g_h[n] = 0.5f * s;
}

// ---------------- K2: persistent hi*hi GEMM sweep + per-tile min ----------
// 128 CTAs, 256 threads. Each CTA owns 256 rows; A (256x256 bf16 = 128KB)
// smem-resident; streams all 8192 codes as 128 chunks of 64 codes (512B rows)
// through a 3-stage cp.async ring (stage = 32KB B + 256B h).
#define NCHUNK   128
#define A_BYTES  131072
#define BSTG     33024          // 32768 B + 256 h
#define SMEM_TOT (A_BYTES + 3 * BSTG)   // 230144

__device__ __forceinline__ void issueB(int tid, int c, uint32_t stg) {
    const char* Bg = reinterpret_cast<const char*>(g_Bh);
#pragma unroll
    for (int i = 0; i < 8; i++) {
        int lin = tid + i * 256;              // 0..2047 : 64 rows x 32 chunks
        int row = lin >> 5;
        int ch = lin & 31;
        uint32_t sw = (uint32_t)(row * 512 + ((ch ^ (row & 7)) * 16));
        cp_async16(stg + sw, Bg + (size_t)(c * 64 + row) * 512 + ch * 16);
    }
    if (tid < 16)
        cp_async16(stg + 32768 + tid * 16,
                   reinterpret_cast<const char*>(g_h) + c * 256 + tid * 16);
}

__global__ void __launch_bounds__(256, 1)
dist_sweep_kernel() {
    extern __shared__ char smem[];
    const uint32_t sb = smem_u32(smem);
    const int tid = threadIdx.x;
    const int wid = tid >> 5;
    const int l = tid & 31;
    const int warp_m = wid >> 1;          // 0..3 (64 rows)
    const int warp_n = wid & 1;           // 0..1 (32 cols)
    const int m0 = blockIdx.x * 256;

    // load A resident (256 rows x 512B, swizzled)
    {
        const char* Ag = reinterpret_cast<const char*>(g_Ah);
        for (int i = tid; i < 8192; i += 256) {       // 256 rows x 32 chunks
            int row = i >> 5;
            int ch = i & 31;
            uint32_t sw = (uint32_t)(row * 512 + ((ch ^ (row & 7)) * 16));
            cp_async16(sb + sw, Ag + (size_t)(m0 + row) * 512 + ch * 16);
        }
    }
    issueB(tid, 0, sb + A_BYTES + 0 * BSTG); cp_commit();   // group0 = A + B0
    issueB(tid, 1, sb + A_BYTES + 1 * BSTG); cp_commit();   // group1 = B1

    const int a_r = (l & 15);
    const int a_half = l >> 4;
    const int b_r = (l & 7) + ((l >> 4) << 3);
    const int b_half = (l >> 3) & 1;
    const int g = l >> 2;
    const int tg = l & 3;

    // per-row running minima: rows warp_m*64 + mi*16 + g (+8)
    float pv[4][2];
    int pi[4][2];
#pragma unroll
    for (int mi = 0; mi < 4; mi++) {
        pv[mi][0] = __int_as_float(0x7f800000);
        pv[mi][1] = __int_as_float(0x7f800000);
        pi[mi][0] = 0; pi[mi][1] = 0;
    }

    for (int c = 0; c < NCHUNK; c++) {
        if (c + 2 < NCHUNK) cp_wait1(); else cp_wait0();
        __syncthreads();
        if (c + 2 < NCHUNK) {
            issueB(tid, c + 2, sb + A_BYTES + ((c + 2) % 3) * BSTG);
            cp_commit();
        }
        const uint32_t Bs = sb + A_BYTES + (c % 3) * BSTG;
        const float* h_s = reinterpret_cast<const float*>(smem + A_BYTES +
                                                          (c % 3) * BSTG + 32768);
        float acc[4][4][4];
#pragma unroll
        for (int mi = 0; mi < 4; mi++)
#pragma unroll
            for (int ni = 0; ni < 4; ni++)
#pragma unroll
                for (int f = 0; f < 4; f++) acc[mi][ni][f] = 0.0f;

#pragma unroll
        for (int ks = 0; ks < 16; ks++) {
            uint32_t a[4][4];
#pragma unroll
            for (int mi = 0; mi < 4; mi++) {
                int row = warp_m * 64 + mi * 16 + a_r;
                uint32_t addr = sb + row * 512 +
                                (((ks * 2 + a_half) ^ (row & 7)) * 16);
                ldsm4(a[mi][0], a[mi][1], a[mi][2], a[mi][3], addr);
            }
            uint32_t b[4][2];
#pragma unroll
            for (int nb = 0; nb < 2; nb++) {
                int row = warp_n * 32 + nb * 16 + b_r;
                uint32_t addr = Bs + row * 512 +
                                (((ks * 2 + b_half) ^ (row & 7)) * 16);
                uint32_t r0, r1, r2, r3;
                ldsm4(r0, r1, r2, r3, addr);
                b[nb * 2 + 0][0] = r0; b[nb * 2 + 0][1] = r1;
                b[nb * 2 + 1][0] = r2; b[nb * 2 + 1][1] = r3;
            }
#pragma unroll
            for (int mi = 0; mi < 4; mi++)
#pragma unroll
                for (int ni = 0; ni < 4; ni++)
                    mma16816(acc[mi][ni][0], acc[mi][ni][1],
                             acc[mi][ni][2], acc[mi][ni][3],
                             a[mi][0], a[mi][1], a[mi][2], a[mi][3],
                             b[ni][0], b[ni][1]);
        }

        // update running minima: s = 0.5|e|^2 - dot_hi
        const int cbase = c * 64;
#pragma unroll
        for (int ni = 0; ni < 4; ni++) {
            int col = warp_n * 32 + ni * 8 + 2 * tg;
            float h0 = h_s[col], h1 = h_s[col + 1];
            int gi0 = cbase + col, gi1 = gi0 + 1;
#pragma unroll
            for (int mi = 0; mi < 4; mi++) {
                float s0 = h0 - acc[mi][ni][0];
                float s1 = h1 - acc[mi][ni][1];
                float s2 = h0 - acc[mi][ni][2];
                float s3 = h1 - acc[mi][ni][3];
                if (s0 < pv[mi][0]) { pv[mi][0] = s0; pi[mi][0] = gi0; }
                if (s1 < pv[mi][0]) { pv[mi][0] = s1; pi[mi][0] = gi1; }
                if (s2 < pv[mi][1]) { pv[mi][1] = s2; pi[mi][1] = gi0; }
                if (s3 < pv[mi][1]) { pv[mi][1] = s3; pi[mi][1] = gi1; }
            }
        }

        if (c & 1) {  // flush tile (c>>1)
            int tile = c >> 1;
#pragma unroll
            for (int mi = 0; mi < 4; mi++) {
#pragma unroll
                for (int hh = 0; hh < 2; hh++) {
                    unsigned long long key =
                        ((unsigned long long)fkey(pv[mi][hh]) << 32) |
                        (unsigned int)pi[mi][hh];
#pragma unroll
                    for (int off = 1; off <= 2; off <<= 1)
                        key = ullmin2(key, __shfl_xor_sync(0xFFFFFFFFu, key, off));
                    if (tg == 0) {
                        int row = m0 + warp_m * 64 + mi * 16 + g + hh * 8;
                        atomicMin(&g_part[(size_t)row * NTILES + tile], key);
                    }
                    pv[mi][hh] = __int_as_float(0x7f800000);
                }
            }
        }
    }
}

// ---------------- K3: Phase B — global approx min + active-tile lists -----
__global__ void cand_kernel() {
    int w = threadIdx.x >> 5;
    int l = threadIdx.x & 31;
    int row = blockIdx.x * 8 + w;
    unsigned long long k0 = g_part[(size_t)row * NTILES + l];
    unsigned long long k1 = g_part[(size_t)row * NTILES + 32 + l];
    unsigned long long km = ullmin2(k0, k1);
#pragma unroll
    for (int off = 16; off; off >>= 1)
        km = ullmin2(km, __shfl_xor_sync(0xFFFFFFFFu, km, off));
    float thresh = inv_fkey((unsigned int)(km >> 32)) + MARGIN;
    if (inv_fkey((unsigned int)(k0 >> 32)) < thresh) {
        int p = atomicAdd(&g_tcnt[l], 1);
        g_tlist[l * NROWS + p] = row;
    }
    if (inv_fkey((unsigned int)(k1 >> 32)) < thresh) {
        int p = atomicAdd(&g_tcnt[32 + l], 1);
        g_tlist[(32 + l) * NROWS + p] = row;
    }
}

// ---------------- K4: Phase C — exact fp32 refine over active tiles -------
#define NSLICE 8
#define ESTR 257
#define RSMEM ((128 * ESTR + 264 + 128 + 128) * 4 + 32)

__global__ void __launch_bounds__(256, 1)
refine_kernel(const float* __restrict__ emb, const float* __restrict__ z) {
    extern __shared__ float sm[];
    float* e_s = sm;
    float* z_s = sm + 128 * ESTR;
    float* pp  = z_s + 264;
    float* h_s = pp + 128;
    unsigned long long* red = (unsigned long long*)(h_s + 128);
    const int t = blockIdx.x & (NTILES - 1);
    const int slice = blockIdx.x >> 6;
    const int tid = threadIdx.x;

    for (int idx = tid; idx < 128 * 64; idx += 256) {
        int r = idx >> 6, c4 = (idx & 63) * 4;
        float4 v = *reinterpret_cast<const float4*>(&emb[(t * 128 + r) * DIM + c4]);
        float* d = &e_s[r * ESTR + c4];
        d[0] = v.x; d[1] = v.y; d[2] = v.z; d[3] = v.w;
    }
    if (tid < 128) h_s[tid] = g_h[t * 128 + tid];
    __syncthreads();

    const int n = g_tcnt[t];
    const int c = tid & 127;
    const int half = tid >> 7;
    const int k0 = half * 128;

    for (int i = slice; i < n; i += NSLICE) {
        int row = g_tlist[t * NROWS + i];
        if (tid < 64) {
            float4 v = *reinterpret_cast<const float4*>(&z[row * DIM + tid * 4]);
            float* d = &z_s[tid * 4];
            d[0] = v.x; d[1] = v.y; d[2] = v.z; d[3] = v.w;
        }
        __syncthreads();
        float dot = 0.0f;
#pragma unroll 8
        for (int k = 0; k < 128; k++)
            dot += e_s[c * ESTR + k0 + k] * z_s[k0 + k];
        if (half) pp[c] = dot;
        __syncthreads();
        if (!half) {
            float s = h_s[c] - (dot + pp[c]);
            unsigned long long key =
                ((unsigned long long)fkey(s) << 32) | (unsigned int)(t * 128 + c);
#pragma unroll
            for (int off = 16; off; off >>= 1)
                key = ullmin2(key, __shfl_xor_sync(0xFFFFFFFFu, key, off));
            if ((c & 31) == 0) red[c >> 5] = key;
        }
        __syncthreads();
        if (tid == 0) {
            unsigned long long b =
                ullmin2(ullmin2(red[0], red[1]), ullmin2(red[2], red[3]));
            atomicMin(&g_keys[row], b);
        }
        __syncthreads();
    }
}

// ---------------- K5: gather z_q, loss partials, scatter counts/dw -------
__global__ void assign_kernel(const float* __restrict__ z,
                              const float* __restrict__ emb,
                              float* __restrict__ out) {
    int t = threadIdx.x;
    int row = blockIdx.x * 4 + (t >> 6);
    int c = (t & 63) * 4;
    int idx = (int)(g_keys[row] & 0xFFFFFFFFull);
    float4 zv = *reinterpret_cast<const float4*>(&z[row * DIM + c]);
    float4 ev = *reinterpret_cast<const float4*>(&emb[idx * DIM + c]);
    float4 q;
    q.x = zv.x + (ev.x - zv.x);
    q.y = zv.y + (ev.y - zv.y);
    q.z = zv.z + (ev.z - zv.z);
    q.w = zv.w + (ev.w - zv.w);
    *reinterpret_cast<float4*>(&out[ZQ_OFF + row * DIM + c]) = q;
    float dx = ev.x - zv.x, dy = ev.y - zv.y, dz = ev.z - zv.z, dw = ev.w - zv.w;
    float v = dx * dx + dy * dy + dz * dz + dw * dw;
#pragma unroll
    for (int off = 16; off; off >>= 1) v += __shfl_down_sync(0xFFFFFFFFu, v, off);
    __shared__ float red[8];
    if ((t & 31) == 0) red[t >> 5] = v;
    __syncthreads();
    if (t == 0) {
        float s = 0.0f;
#pragma unroll
        for (int w = 0; w < 8; w++) s += red[w];
        atomicAdd(&g_loss_sum, s);
    }
    if ((t & 63) == 0) {
        atomicAdd(&g_counts[idx], 1.0f);
        out[IDX_OFF + row] = (float)idx;
    }
    float* dwp = &g_dw[idx * DIM + c];
    atomicAdd(dwp + 0, zv.x);
    atomicAdd(dwp + 1, zv.y);
    atomicAdd(dwp + 2, zv.z);
    atomicAdd(dwp + 3, zv.w);
}

// ---------------- K6: new_cluster_size + n = sum -------------------------
__global__ void ncs_kernel(const float* __restrict__ ecs, float* __restrict__ out) {
    int t = threadIdx.x;
    float s = 0.0f;
#pragma unroll
    for (int j = 0; j < KCODES / 1024; j++) {
        int k = t + j * 1024;
        float v = ecs[k] * DECAY_F + OMD_F * g_counts[k];
        out[NCS_OFF + k] = v;
        s += v;
    }
#pragma unroll
    for (int off = 16; off; off >>= 1) s += __shfl_down_sync(0xFFFFFFFFu, s, off);
    __shared__ float red[32];
    if ((t & 31) == 0) red[t >> 5] = s;
    __syncthreads();
    if (t == 0) {
        float tot = 0.0f;
#pragma unroll
        for (int w = 0; w < 32; w++) tot += red[w];
        g_n_tot = tot;
    }
}

// ---------------- K7: new_ema_w, new_embedding, loss ---------------------
__global__ void final_kernel(const float* __restrict__ emaw, float* __restrict__ out) {
    int k = blockIdx.x;
    int d = threadIdx.x;
    float ncs = out[NCS_OFF + k];
    float n = g_n_tot;
    float cs = (ncs + EPSV) / (n + (float)KCODES * EPSV) * n;
    int e = k * DIM + d;
    float w = emaw[e] * DECAY_F + OMD_F * g_dw[e];
    out[NEMAW_OFF + e] = w;
    out[NEMB_OFF + e] = w / cs;
    if (k == 0 && d == 0)
        out[LOSS_OFF] = CCOST * g_loss_sum / (float)((long long)NROWS * DIM);
}

// ---------------- launch -------------------------------------------------
extern "C" void kernel_launch(void* const* d_in, const int* in_sizes, int n_in,
                              void* d_out, int out_size) {
    const float* z    = (const float*)d_in[0];
    const float* emb  = (const float*)d_in[1];
    const float* ecs  = (const float*)d_in[2];
    const float* emaw = (const float*)d_in[3];
    float* out = (float*)d_out;

    cudaFuncSetAttribute(dist_sweep_kernel,
                         cudaFuncAttributeMaxDynamicSharedMemorySize, SMEM_TOT);
    cudaFuncSetAttribute(refine_kernel,
                         cudaFuncAttributeMaxDynamicSharedMemorySize, RSMEM);

    init_kernel<<<(KCODES * DIM + 255) / 256, 256>>>();
    pack_z_kernel<<<(NROWS * DIM / 4 + 255) / 256, 256>>>(z);
    pack_e_kernel<<<(KCODES * DIM / 4 + 255) / 256, 256>>>(emb);
    h_kernel<<<KCODES / 8, 256>>>(emb);
    dist_sweep_kernel<<<NROWS / 256, 256, SMEM_TOT>>>();
    cand_kernel<<<NROWS / 8, 256>>>();
    refine_kernel<<<NTILES * NSLICE, 256, RSMEM>>>(emb, z);
    assign_kernel<<<NROWS / 4, 256>>>(z, emb, out);
    ncs_kernel<<<1, 1024>>>(ecs, out);
    final_kernel<<<KCODES, DIM>>>(emaw, out);
}

// round 17
// speedup vs baseline: 1.0013x; 1.0013x over previous
#include <cuda_runtime.h>
#include <cuda_bf16.h>
#include <cstdint>

#define NROWS   32768
#define KCODES  8192
#define DIM     256
#define NTILES  64             // KCODES / 128
#define MARGIN  1.0f
#define DECAY_F 0.99f
#define OMD_F   0.01f
#define EPSV    1e-5f
#define CCOST   0.25f

// output layout (flattened, reference return order, all f32)
#define ZQ_OFF    0
#define LOSS_OFF  8388608
#define IDX_OFF   8388609
#define NEMB_OFF  8421377
#define NCS_OFF   10518529
#define NEMAW_OFF 10526721

// ---------------- scratch (static device globals; no allocs) ----------------
__device__ unsigned long long g_keys[NROWS];
__device__ unsigned long long g_part[NROWS * NTILES];   // per (row, tile) approx min-key
__device__ int g_tcnt[NTILES];
__device__ int g_tlist[NTILES * NROWS];
__device__ float g_h[KCODES];
__device__ float g_counts[KCODES];
__device__ float g_dw[KCODES * DIM];
__device__ float g_loss_sum;
__device__ float g_n_tot;
__device__ __nv_bfloat16 g_Ah[NROWS * DIM];    // z_hi (bf16), 512B rows
__device__ __nv_bfloat16 g_Bh[KCODES * DIM];   // e_hi (bf16), 512B rows

// ---------------- helpers ----------------
__device__ __forceinline__ unsigned int fkey(float f) {
    unsigned int u = __float_as_uint(f);
    return (u & 0x80000000u) ? ~u : (u | 0x80000000u);
}
__device__ __forceinline__ float inv_fkey(unsigned int k) {
    unsigned int u = (k & 0x80000000u) ? (k & 0x7FFFFFFFu) : ~k;
    return __uint_as_float(u);
}
__device__ __forceinline__ unsigned long long ullmin2(unsigned long long a,
                                                      unsigned long long b) {
    return a < b ? a : b;
}
__device__ __forceinline__ uint32_t smem_u32(const void* p) {
    uint32_t a;
    asm("{ .reg .u64 t; cvta.to.shared.u64 t, %1; cvt.u32.u64 %0, t; }"
        : "=r"(a) : "l"(p));
    return a;
}
__device__ __forceinline__ void cp_async16(uint32_t smem, const void* g) {
    asm volatile("cp.async.cg.shared.global [%0], [%1], 16;"
                 :: "r"(smem), "l"(g));
}
__device__ __forceinline__ void cp_commit() {
    asm volatile("cp.async.commit_group;");
}
__device__ __forceinline__ void cp_wait1() {
    asm volatile("cp.async.wait_group 1;");
}
__device__ __forceinline__ void cp_wait0() {
    asm volatile("cp.async.wait_group 0;");
}
__device__ __forceinline__ void ldsm4(uint32_t& r0, uint32_t& r1, uint32_t& r2,
                                      uint32_t& r3, uint32_t addr) {
    asm volatile("ldmatrix.sync.aligned.m8n8.x4.shared.b16 {%0,%1,%2,%3}, [%4];"
                 : "=r"(r0), "=r"(r1), "=r"(r2), "=r"(r3) : "r"(addr));
}
__device__ __forceinline__ void mma16816(float& c0, float& c1, float& c2, float& c3,
                                         uint32_t a0, uint32_t a1, uint32_t a2,
                                         uint32_t a3, uint32_t b0, uint32_t b1) {
    asm volatile(
        "mma.sync.aligned.m16n8k16.row.col.f32.bf16.bf16.f32 "
        "{%0,%1,%2,%3}, {%4,%5,%6,%7}, {%8,%9}, {%0,%1,%2,%3};"
        : "+f"(c0), "+f"(c1), "+f"(c2), "+f"(c3)
        : "r"(a0), "r"(a1), "r"(a2), "r"(a3), "r"(b0), "r"(b1));
}

// ---------------- K0: zero scratch ----------------
__global__ void init_kernel() {
    int i = blockIdx.x * blockDim.x + threadIdx.x;
    if (i < KCODES * DIM) g_dw[i] = 0.0f;
    if (i < NROWS * NTILES) g_part[i] = 0xFFFFFFFFFFFFFFFFull;
    if (i < NROWS) g_keys[i] = 0xFFFFFFFFFFFFFFFFull;
    if (i < KCODES) g_counts[i] = 0.0f;
    if (i < NTILES) g_tcnt[i] = 0;
    if (i == 0) g_loss_sum = 0.0f;
}

// ---------------- K0b: bf16 hi pack ----------------
__global__ void pack_z_kernel(const float* __restrict__ z) {
    int i = blockIdx.x * blockDim.x + threadIdx.x;
    if (i >= NROWS * DIM / 4) return;
    float4 v = reinterpret_cast<const float4*>(z)[i];
    __nv_bfloat162 h0 = __float22bfloat162_rn(make_float2(v.x, v.y));
    __nv_bfloat162 h1 = __float22bfloat162_rn(make_float2(v.z, v.w));
    __nv_bfloat162* d = reinterpret_cast<__nv_bfloat162*>(&g_Ah[i * 4]);
    d[0] = h0; d[1] = h1;
}
__global__ void pack_e_kernel(const float* __restrict__ e) {
    int i = blockIdx.x * blockDim.x + threadIdx.x;
    if (i >= KCODES * DIM / 4) return;
    float4 v = reinterpret_cast<const float4*>(e)[i];
    __nv_bfloat162 h0 = __float22bfloat162_rn(make_float2(v.x, v.y));
    __nv_bfloat162 h1 = __float22bfloat162_rn(make_float2(v.z, v.w));
    __nv_bfloat162* d = reinterpret_cast<__nv_bfloat162*>(&g_Bh[i * 4]);
    d[0] = h0; d[1] = h1;
}

// ---------------- K1: h[k] = 0.5*|e_k|^2 (exact fp32) ----------------
__global__ void h_kernel(const float* __restrict__ emb) {
    int lane = threadIdx.x & 31;
    int n = blockIdx.x * 8 + (threadIdx.x >> 5);
    float s = 0.0f;
#pragma unroll
    for (int j = 0; j < 8; j++) {
        float v = emb[n * DIM + lane + j * 32];
        s += v * v;
    }
#pragma unroll
    for (int off = 16; off; off >>= 1) s += __shfl_down_sync(0xFFFFFFFFu, s, off);
    if (lane == 0) g_h[n] = 0.5f * s;
}

// ---------------- K2: persistent hi*hi GEMM sweep + per-tile min ----------
// 128 CTAs, 256 threads. Each CTA owns 256 rows; A (256x256 bf16 = 128KB)
// smem-resident; streams all 8192 codes as 128 chunks of 64 codes (512B rows)
// through a 3-stage cp.async ring (stage = 32KB B + 256B h).
#define NCHUNK   128
#define A_BYTES  131072
#define BSTG     33024          // 32768 B + 256 h
#define SMEM_TOT (A_BYTES + 3 * BSTG)   // 230144

__device__ __forceinline__ void issueB(int tid, int c, uint32_t stg) {
    const char* Bg = reinterpret_cast<const char*>(g_Bh);
#pragma unroll
    for (int i = 0; i < 8; i++) {
        int lin = tid + i * 256;              // 0..2047 : 64 rows x 32 chunks
        int row = lin >> 5;
        int ch = lin & 31;
        uint32_t sw = (uint32_t)(row * 512 + ((ch ^ (row & 7)) * 16));
        cp_async16(stg + sw, Bg + (size_t)(c * 64 + row) * 512 + ch * 16);
    }
    if (tid < 16)
        cp_async16(stg + 32768 + tid * 16,
                   reinterpret_cast<const char*>(g_h) + c * 256 + tid * 16);
}

__global__ void __launch_bounds__(256, 1)
dist_sweep_kernel() {
    extern __shared__ char smem[];
    const uint32_t sb = smem_u32(smem);
    const int tid = threadIdx.x;
    const int wid = tid >> 5;
    const int l = tid & 31;
    const int warp_m = wid >> 1;          // 0..3 (64 rows)
    const int warp_n = wid & 1;           // 0..1 (32 cols)
    const int m0 = blockIdx.x * 256;

    // load A resident (256 rows x 512B, swizzled)
    {
        const char* Ag = reinterpret_cast<const char*>(g_Ah);
        for (int i = tid; i < 8192; i += 256) {       // 256 rows x 32 chunks
            int row = i >> 5;
            int ch = i & 31;
            uint32_t sw = (uint32_t)(row * 512 + ((ch ^ (row & 7)) * 16));
            cp_async16(sb + sw, Ag + (size_t)(m0 + row) * 512 + ch * 16);
        }
    }
    issueB(tid, 0, sb + A_BYTES + 0 * BSTG); cp_commit();   // group0 = A + B0
    issueB(tid, 1, sb + A_BYTES + 1 * BSTG); cp_commit();   // group1 = B1

    const int a_r = (l & 15);
    const int a_half = l >> 4;
    const int b_r = (l & 7) + ((l >> 4) << 3);
    const int b_half = (l >> 3) & 1;
    const int g = l >> 2;
    const int tg = l & 3;

    // per-row running minima: rows warp_m*64 + mi*16 + g (+8)
    float pv[4][2];
    int pi[4][2];
#pragma unroll
    for (int mi = 0; mi < 4; mi++) {
        pv[mi][0] = __int_as_float(0x7f800000);
        pv[mi][1] = __int_as_float(0x7f800000);
        pi[mi][0] = 0; pi[mi][1] = 0;
    }

    for (int c = 0; c < NCHUNK; c++) {
        if (c + 2 < NCHUNK) cp_wait1(); else cp_wait0();
        __syncthreads();
        if (c + 2 < NCHUNK) {
            issueB(tid, c + 2, sb + A_BYTES + ((c + 2) % 3) * BSTG);
            cp_commit();
        }
        const uint32_t Bs = sb + A_BYTES + (c % 3) * BSTG;
        const float* h_s = reinterpret_cast<const float*>(smem + A_BYTES +
                                                          (c % 3) * BSTG + 32768);
        float acc[4][4][4];
#pragma unroll
        for (int mi = 0; mi < 4; mi++)
#pragma unroll
            for (int ni = 0; ni < 4; ni++)
#pragma unroll
                for (int f = 0; f < 4; f++) acc[mi][ni][f] = 0.0f;

#pragma unroll
        for (int ks = 0; ks < 16; ks++) {
            uint32_t a[4][4];
#pragma unroll
            for (int mi = 0; mi < 4; mi++) {
                int row = warp_m * 64 + mi * 16 + a_r;
                uint32_t addr = sb + row * 512 +
                                (((ks * 2 + a_half) ^ (row & 7)) * 16);
                ldsm4(a[mi][0], a[mi][1], a[mi][2], a[mi][3], addr);
            }
            uint32_t b[4][2];
#pragma unroll
            for (int nb = 0; nb < 2; nb++) {
                int row = warp_n * 32 + nb * 16 + b_r;
                uint32_t addr = Bs + row * 512 +
                                (((ks * 2 + b_half) ^ (row & 7)) * 16);
                uint32_t r0, r1, r2, r3;
                ldsm4(r0, r1, r2, r3, addr);
                b[nb * 2 + 0][0] = r0; b[nb * 2 + 0][1] = r1;
                b[nb * 2 + 1][0] = r2; b[nb * 2 + 1][1] = r3;
            }
#pragma unroll
            for (int mi = 0; mi < 4; mi++)
#pragma unroll
                for (int ni = 0; ni < 4; ni++)
                    mma16816(acc[mi][ni][0], acc[mi][ni][1],
                             acc[mi][ni][2], acc[mi][ni][3],
                             a[mi][0], a[mi][1], a[mi][2], a[mi][3],
                             b[ni][0], b[ni][1]);
        }

        // update running minima: s = 0.5|e|^2 - dot_hi
        const int cbase = c * 64;
#pragma unroll
        for (int ni = 0; ni < 4; ni++) {
            int col = warp_n * 32 + ni * 8 + 2 * tg;
            float h0 = h_s[col], h1 = h_s[col + 1];
            int gi0 = cbase + col, gi1 = gi0 + 1;
#pragma unroll
            for (int mi = 0; mi < 4; mi++) {
                float s0 = h0 - acc[mi][ni][0];
                float s1 = h1 - acc[mi][ni][1];
                float s2 = h0 - acc[mi][ni][2];
                float s3 = h1 - acc[mi][ni][3];
                if (s0 < pv[mi][0]) { pv[mi][0] = s0; pi[mi][0] = gi0; }
                if (s1 < pv[mi][0]) { pv[mi][0] = s1; pi[mi][0] = gi1; }
                if (s2 < pv[mi][1]) { pv[mi][1] = s2; pi[mi][1] = gi0; }
                if (s3 < pv[mi][1]) { pv[mi][1] = s3; pi[mi][1] = gi1; }
            }
        }

        if (c & 1) {  // flush tile (c>>1)
            int tile = c >> 1;
#pragma unroll
            for (int mi = 0; mi < 4; mi++) {
#pragma unroll
                for (int hh = 0; hh < 2; hh++) {
                    unsigned long long key =
                        ((unsigned long long)fkey(pv[mi][hh]) << 32) |
                        (unsigned int)pi[mi][hh];
#pragma unroll
                    for (int off = 1; off <= 2; off <<= 1)
                        key = ullmin2(key, __shfl_xor_sync(0xFFFFFFFFu, key, off));
                    if (tg == 0) {
                        int row = m0 + warp_m * 64 + mi * 16 + g + hh * 8;
                        atomicMin(&g_part[(size_t)row * NTILES + tile], key);
                    }
                    pv[mi][hh] = __int_as_float(0x7f800000);
                }
            }
        }
    }
}

// ---------------- K3: Phase B — global approx min + active-tile lists -----
__global__ void cand_kernel() {
    int w = threadIdx.x >> 5;
    int l = threadIdx.x & 31;
    int row = blockIdx.x * 8 + w;
    unsigned long long k0 = g_part[(size_t)row * NTILES + l];
    unsigned long long k1 = g_part[(size_t)row * NTILES + 32 + l];
    unsigned long long km = ullmin2(k0, k1);
#pragma unroll
    for (int off = 16; off; off >>= 1)
        km = ullmin2(km, __shfl_xor_sync(0xFFFFFFFFu, km, off));
    float thresh = inv_fkey((unsigned int)(km >> 32)) + MARGIN;
    if (inv_fkey((unsigned int)(k0 >> 32)) < thresh) {
        int p = atomicAdd(&g_tcnt[l], 1);
        g_tlist[l * NROWS + p] = row;
    }
    if (inv_fkey((unsigned int)(k1 >> 32)) < thresh) {
        int p = atomicAdd(&g_tcnt[32 + l], 1);
        g_tlist[(32 + l) * NROWS + p] = row;
    }
}

// ---------------- K4: Phase C — exact fp32 refine over active tiles -------
#define NSLICE 8
#define ESTR 257
#define RSMEM ((128 * ESTR + 264 + 128 + 128) * 4 + 32)

__global__ void __launch_bounds__(256, 1)
refine_kernel(const float* __restrict__ emb, const float* __restrict__ z) {
    extern __shared__ float sm[];
    float* e_s = sm;
    float* z_s = sm + 128 * ESTR;
    float* pp  = z_s + 264;
    float* h_s = pp + 128;
    unsigned long long* red = (unsigned long long*)(h_s + 128);
    const int t = blockIdx.x & (NTILES - 1);
    const int slice = blockIdx.x >> 6;
    const int tid = threadIdx.x;

    for (int idx = tid; idx < 128 * 64; idx += 256) {
        int r = idx >> 6, c4 = (idx & 63) * 4;
        float4 v = *reinterpret_cast<const float4*>(&emb[(t * 128 + r) * DIM + c4]);
        float* d = &e_s[r * ESTR + c4];
        d[0] = v.x; d[1] = v.y; d[2] = v.z; d[3] = v.w;
    }
    if (tid < 128) h_s[tid] = g_h[t * 128 + tid];
    __syncthreads();

    const int n = g_tcnt[t];
    const int c = tid & 127;
    const int half = tid >> 7;
    const int k0 = half * 128;

    for (int i = slice; i < n; i += NSLICE) {
        int row = g_tlist[t * NROWS + i];
        if (tid < 64) {
            float4 v = *reinterpret_cast<const float4*>(&z[row * DIM + tid * 4]);
            float* d = &z_s[tid * 4];
            d[0] = v.x; d[1] = v.y; d[2] = v.z; d[3] = v.w;
        }
        __syncthreads();
        float dot = 0.0f;
#pragma unroll 8
        for (int k = 0; k < 128; k++)
            dot += e_s[c * ESTR + k0 + k] * z_s[k0 + k];
        if (half) pp[c] = dot;
        __syncthreads();
        if (!half) {
            float s = h_s[c] - (dot + pp[c]);
            unsigned long long key =
                ((unsigned long long)fkey(s) << 32) | (unsigned int)(t * 128 + c);
#pragma unroll
            for (int off = 16; off; off >>= 1)
                key = ullmin2(key, __shfl_xor_sync(0xFFFFFFFFu, key, off));
            if ((c & 31) == 0) red[c >> 5] = key;
        }
        __syncthreads();
        if (tid == 0) {
            unsigned long long b =
                ullmin2(ullmin2(red[0], red[1]), ullmin2(red[2], red[3]));
            atomicMin(&g_keys[row], b);
        }
        __syncthreads();
    }
}

// ---------------- K5: gather z_q, loss partials, scatter counts/dw -------
__global__ void assign_kernel(const float* __restrict__ z,
                              const float* __restrict__ emb,
                              float* __restrict__ out) {
    int t = threadIdx.x;
    int row = blockIdx.x * 4 + (t >> 6);
    int c = (t & 63) * 4;
    int idx = (int)(g_keys[row] & 0xFFFFFFFFull);
    float4 zv = *reinterpret_cast<const float4*>(&z[row * DIM + c]);
    float4 ev = *reinterpret_cast<const float4*>(&emb[idx * DIM + c]);
    float4 q;
    q.x = zv.x + (ev.x - zv.x);
    q.y = zv.y + (ev.y - zv.y);
    q.z = zv.z + (ev.z - zv.z);
    q.w = zv.w + (ev.w - zv.w);
    *reinterpret_cast<float4*>(&out[ZQ_OFF + row * DIM + c]) = q;
    float dx = ev.x - zv.x, dy = ev.y - zv.y, dz = ev.z - zv.z, dw = ev.w - zv.w;
    float v = dx * dx + dy * dy + dz * dz + dw * dw;
#pragma unroll
    for (int off = 16; off; off >>= 1) v += __shfl_down_sync(0xFFFFFFFFu, v, off);
    __shared__ float red[8];
    if ((t & 31) == 0) red[t >> 5] = v;
    __syncthreads();
    if (t == 0) {
        float s = 0.0f;
#pragma unroll
        for (int w = 0; w < 8; w++) s += red[w];
        atomicAdd(&g_loss_sum, s);
    }
    if ((t & 63) == 0) {
        atomicAdd(&g_counts[idx], 1.0f);
        out[IDX_OFF + row] = (float)idx;
    }
    float* dwp = &g_dw[idx * DIM + c];
    atomicAdd(dwp + 0, zv.x);
    atomicAdd(dwp + 1, zv.y);
    atomicAdd(dwp + 2, zv.z);
    atomicAdd(dwp + 3, zv.w);
}

// ---------------- K6: new_cluster_size + n = sum -------------------------
__global__ void ncs_kernel(const float* __restrict__ ecs, float* __restrict__ out) {
    int t = threadIdx.x;
    float s = 0.0f;
#pragma unroll
    for (int j = 0; j < KCODES / 1024; j++) {
        int k = t + j * 1024;
        float v = ecs[k] * DECAY_F + OMD_F * g_counts[k];
        out[NCS_OFF + k] = v;
        s += v;
    }
#pragma unroll
    for (int off = 16; off; off >>= 1) s += __shfl_down_sync(0xFFFFFFFFu, s, off);
    __shared__ float red[32];
    if ((t & 31) == 0) red[t >> 5] = s;
    __syncthreads();
    if (t == 0) {
        float tot = 0.0f;
#pragma unroll
        for (int w = 0; w < 32; w++) tot += red[w];
        g_n_tot = tot;
    }
}

// ---------------- K7: new_ema_w, new_embedding, loss ---------------------
__global__ void final_kernel(const float* __restrict__ emaw, float* __restrict__ out) {
    int k = blockIdx.x;
    int d = threadIdx.x;
    float ncs = out[NCS_OFF + k];
    float n = g_n_tot;
    float cs = (ncs + EPSV) / (n + (float)KCODES * EPSV) * n;
    int e = k * DIM + d;
    float w = emaw[e] * DECAY_F + OMD_F * g_dw[e];
    out[NEMAW_OFF + e] = w;
    out[NEMB_OFF + e] = w / cs;
    if (k == 0 && d == 0)
        out[LOSS_OFF] = CCOST * g_loss_sum / (float)((long long)NROWS * DIM);
}

// ---------------- launch -------------------------------------------------
extern "C" void kernel_launch(void* const* d_in, const int* in_sizes, int n_in,
                              void* d_out, int out_size) {
    const float* z    = (const float*)d_in[0];
    const float* emb  = (const float*)d_in[1];
    const float* ecs  = (const float*)d_in[2];
    const float* emaw = (const float*)d_in[3];
    float* out = (float*)d_out;

    cudaFuncSetAttribute(dist_sweep_kernel,
                         cudaFuncAttributeMaxDynamicSharedMemorySize, SMEM_TOT);
    cudaFuncSetAttribute(refine_kernel,
                         cudaFuncAttributeMaxDynamicSharedMemorySize, RSMEM);

    init_kernel<<<(KCODES * DIM + 255) / 256, 256>>>();
    pack_z_kernel<<<(NROWS * DIM / 4 + 255) / 256, 256>>>(z);
    pack_e_kernel<<<(KCODES * DIM / 4 + 255) / 256, 256>>>(emb);
    h_kernel<<<KCODES / 8, 256>>>(emb);
    dist_sweep_kernel<<<NROWS / 256, 256, SMEM_TOT>>>();
    cand_kernel<<<NROWS / 8, 256>>>();
    refine_kernel<<<NTILES * NSLICE, 256, RSMEM>>>(emb, z);
    assign_kernel<<<NROWS / 4, 256>>>(z, emb, out);
    ncs_kernel<<<1, 1024>>>(ecs, out);
    final_kernel<<<KCODES, DIM>>>(emaw, out);
}